// round 15
// baseline (speedup 1.0000x reference)
#include <cuda_runtime.h>
#include <cuda_bf16.h>
#include <cstdint>

#define ALPHA   0.2f          // DT/TAU = 20/100
#define NN      2048
#define BB      64
#define TT      200
#define NI      32
#define NO      8
#define G_CTAS  128
#define N_TILE  16            // neurons per CTA

// Global act layout per step: 8 chunks x (64 rows x 512B), XOR-swizzled:
//   element (b, n): chunk = n>>8, byte kc = (n&255)*2, stored at
//   chunk*32768 + b*512 + (kc ^ ((b&7)<<4))
#define SLOTB       32768
#define STEPB       (8 * SLOTB)        // 262144 bytes per act step

// SMEM offsets
#define OFF_REC     131072             // float[4][64][20] = 20480
#define REC_LD      20
#define REC_PLANE   (64 * REC_LD)
#define OFF_HSM     151552             // float[64][16] = 4096
#define OFF_U       155648             // float[2][64][32] = 16384 (u rows, double buffer)
#define OFF_INW     172032             // float[32][16] = 2048 (In_w transposed)
#define OFF_OW      174080             // float[16][8] = 512
#define OFF_MBAR    174592             // 4 full + 4 empty = 64
#define SMEM_BYTES  174720

// ---------------- device scratch ----------------
__device__ __nv_bfloat16  d_act_bf16[(size_t)(TT + 1) * BB * NN];    // swizzled layout
__device__ unsigned int   d_flag[(TT + 1) * 8 * 32];                 // per-(t,chunk), 128B apart
__device__ float          d_yp[(size_t)(TT + 1) * G_CTAS * BB * NO];

// ---------------- PTX helpers ----------------
__device__ __forceinline__ unsigned ld_acquire_gpu(const unsigned* p) {
    unsigned v;
    asm volatile("ld.acquire.gpu.u32 %0, [%1];" : "=r"(v) : "l"(p) : "memory");
    return v;
}
__device__ __forceinline__ void red_release_add(unsigned* p, unsigned v) {
    asm volatile("red.release.gpu.global.add.u32 [%0], %1;" :: "l"(p), "r"(v) : "memory");
}
__device__ __forceinline__ void mbar_init(uint32_t mbar, uint32_t count) {
    asm volatile("mbarrier.init.shared.b64 [%0], %1;" :: "r"(mbar), "r"(count) : "memory");
}
__device__ __forceinline__ void mbar_expect_tx(uint32_t mbar, uint32_t bytes) {
    asm volatile("mbarrier.arrive.expect_tx.shared.b64 _, [%0], %1;" :: "r"(mbar), "r"(bytes) : "memory");
}
__device__ __forceinline__ void mbar_arrive(uint32_t mbar) {
    asm volatile("mbarrier.arrive.shared.b64 _, [%0];" :: "r"(mbar) : "memory");
}
__device__ __forceinline__ void mbar_wait(uint32_t mbar, int parity) {
    asm volatile(
        "{\n\t.reg .pred P;\n"
        "W%=:\n\t"
        "mbarrier.try_wait.parity.shared.b64 P, [%0], %1;\n\t"
        "@P bra D%=;\n\t"
        "bra W%=;\n"
        "D%=:\n\t}"
        :: "r"(mbar), "r"(parity) : "memory");
}
__device__ __forceinline__ void bulk_cp8k(uint32_t dst, const void* src, uint32_t mbar) {
    asm volatile(
        "cp.async.bulk.shared::cluster.global.mbarrier::complete_tx::bytes [%0], [%1], %2, [%3];"
        :: "r"(dst), "l"(src), "r"(8192u), "r"(mbar) : "memory");
}
__device__ __forceinline__ void cp_async16(void* dst_smem, const void* src_gmem) {
    unsigned s = (unsigned)__cvta_generic_to_shared(dst_smem);
    asm volatile("cp.async.ca.shared.global [%0], [%1], 16;" :: "r"(s), "l"(src_gmem) : "memory");
}
__device__ __forceinline__ void ldm_x4(uint32_t& a0, uint32_t& a1, uint32_t& a2, uint32_t& a3,
                                       uint32_t addr) {
    asm volatile("ldmatrix.sync.aligned.m8n8.x4.shared.b16 {%0,%1,%2,%3}, [%4];"
                 : "=r"(a0), "=r"(a1), "=r"(a2), "=r"(a3) : "r"(addr));
}
__device__ __forceinline__ void mma_16816(float& d0, float& d1, float& d2, float& d3,
                                          uint32_t a0, uint32_t a1, uint32_t a2, uint32_t a3,
                                          uint32_t b0, uint32_t b1) {
    asm volatile("mma.sync.aligned.m16n8k16.row.col.f32.bf16.bf16.f32 "
                 "{%0,%1,%2,%3}, {%4,%5,%6,%7}, {%8,%9}, {%0,%1,%2,%3};"
                 : "+f"(d0), "+f"(d1), "+f"(d2), "+f"(d3)
                 : "r"(a0), "r"(a1), "r"(a2), "r"(a3), "r"(b0), "r"(b1));
}
__device__ __forceinline__ uint32_t pack_bf16x2(float x, float y) {
    __nv_bfloat162 p = __floats2bfloat162_rn(x, y);
    return *(uint32_t*)&p;
}

// ---------------- prep: swizzled act0 + flag init ----------------
__global__ void prep_kernel(const float* __restrict__ h0) {
    int tid = threadIdx.x;   // 256
    char* base = (char*)d_act_bf16;
    int p0 = blockIdx.x * 328;
    int pe = p0 + 328; if (pe > 65536) pe = 65536;
    for (int p = p0 + tid; p < pe; p += 256) {
        int b  = p >> 10;
        int np = p & 1023;
        int chunk = np >> 7;
        int kc    = (np & 127) * 4;
        float t0 = tanhf(h0[2 * np]);
        float t1 = tanhf(h0[2 * np + 1]);
        __nv_bfloat162 v = __floats2bfloat162_rn(t0, t1);
        *(__nv_bfloat162*)(base + chunk * SLOTB + b * 512 + (kc ^ ((b & 7) << 4))) = v;
    }
    if (blockIdx.x == 0) {
        for (int i = tid; i < (TT + 1) * 8; i += 256)
            d_flag[i * 32] = (i < 8) ? 16u : 0u;   // step-0 chunks pre-complete
    }
}

// ---------------- persistent recurrent kernel ----------------
extern __shared__ char smem_raw[];

__global__ void __launch_bounds__(512, 1)
rnn_kernel(const float* __restrict__ J, const float* __restrict__ h0,
           const float* __restrict__ Out_w, const float* __restrict__ u,
           const float* __restrict__ In_w, const float* __restrict__ noise) {
    float* rec   = (float*)(smem_raw + OFF_REC);
    float* hsm   = (float*)(smem_raw + OFF_HSM);
    float* InwSm = (float*)(smem_raw + OFF_INW);
    float* OwSm  = (float*)(smem_raw + OFF_OW);

    const uint32_t smem_u32 = (uint32_t)__cvta_generic_to_shared(smem_raw);
    const uint32_t mb0 = smem_u32 + OFF_MBAR;   // full[s]=+s*8, empty[s]=+32+s*8

    const int tid  = threadIdx.x;
    const int cta  = blockIdx.x;
    const int u0   = cta * N_TILE;
    const int wid  = tid >> 5;
    const int lane = tid & 31;
    const int s    = wid >> 2;          // slot 0..3: consumes chunks s (A) and s+4 (B)
    const int nw   = (wid >> 1) & 1;    // n8 block 0..1
    const int wm   = wid & 1;           // m half (m blocks wm*2, wm*2+1)

    if (tid == 0) {
        #pragma unroll
        for (int i = 0; i < 4; i++) {
            mbar_init(mb0 + i * 8, 1);        // full[i]
            mbar_init(mb0 + 32 + i * 8, 4);   // empty[i]: 4 consumer warps per slot
        }
    }
    for (int idx = tid; idx < BB * N_TILE; idx += 512)
        hsm[idx] = h0[u0 + (idx & (N_TILE - 1))];
    for (int idx = tid; idx < N_TILE * NO; idx += 512)
        OwSm[idx] = Out_w[(size_t)(u0 + idx / NO) * NO + (idx % NO)];
    if (tid < 512) {  // In_w transposed: InwSm[i*16 + r] = In_w[(u0+r)*NI + i]
        int i = tid >> 4, r = tid & 15;
        InwSm[tid] = In_w[(size_t)(u0 + r) * NI + i];
    }

    const int b_row = tid >> 3;            // 0..63
    const int seg   = tid & 7;             // 2 neurons each
    const float krec = ALPHA / (float)NN;

    // stage u[0] and u[1] (double buffer)
    cp_async16(smem_raw + OFF_U + b_row * 128 + seg * 16,
               u + ((size_t)b_row * TT + 0) * NI + seg * 4);
    cp_async16(smem_raw + OFF_U + 8192 + b_row * 128 + seg * 16,
               u + ((size_t)b_row * TT + 1) * NI + seg * 4);
    asm volatile("cp.async.commit_group;" ::: "memory");

    // ---- J -> register-resident B fragments (held for all 200 steps) ----
    const int n_row = u0 + nw * 8 + (lane >> 2);
    const int t4    = lane & 3;
    uint32_t breg[64];   // [0..31]: chunk s; [32..63]: chunk s+4
    {
        const float* JrA = J + (size_t)n_row * NN + s * 256 + 2 * t4;
        #pragma unroll
        for (int i = 0; i < 16; i++) {
            float2 v0 = *(const float2*)(JrA + i * 16);
            float2 v1 = *(const float2*)(JrA + i * 16 + 8);
            breg[2 * i]     = pack_bf16x2(v0.x, v0.y);
            breg[2 * i + 1] = pack_bf16x2(v1.x, v1.y);
        }
        const float* JrB = JrA + 1024;
        #pragma unroll
        for (int i = 0; i < 16; i++) {
            float2 v0 = *(const float2*)(JrB + i * 16);
            float2 v1 = *(const float2*)(JrB + i * 16 + 8);
            breg[32 + 2 * i] = pack_bf16x2(v0.x, v0.y);
            breg[33 + 2 * i] = pack_bf16x2(v1.x, v1.y);
        }
    }

    asm volatile("cp.async.wait_group 0;" ::: "memory");
    __syncthreads();

    // dn(0) in registers
    float dnx, dny;
    {
        float2 nz = *(const float2*)(noise + ((size_t)b_row * TT) * NN + u0 + seg * 2);
        const float* ur = (float*)(smem_raw + OFF_U) + b_row * 32;
        float ax = 0.f, ay = 0.f;
        #pragma unroll
        for (int i = 0; i < 32; i++) {
            float uv = ur[i];
            float2 w = *(float2*)(InwSm + i * 16 + seg * 2);
            ax += uv * w.x; ay += uv * w.y;
        }
        dnx = ALPHA * (ax + nz.x);
        dny = ALPHA * (ay + nz.y);
    }

    // ldmatrix lane constants (swizzled 512B-row slot layout)
    const int row_in_m = (lane & 7) + ((lane >> 3) & 1) * 8;
    const int kb       = (lane >> 4) * 16;
    const int rot      = (row_in_m & 7) << 4;
    const int rot60    = rot & 0x60;
    const uint32_t abase = smem_u32 + s * SLOTB + row_in_m * 512 + (kb ^ (rot & 0x10));
    const uint32_t my_full  = mb0 + s * 8;
    const uint32_t my_empty = mb0 + 32 + s * 8;
    const int g = lane >> 2;
    float* rp   = rec + s * REC_PLANE + nw * 8 + 2 * t4;

    // act writer constants (swizzled global layout)
    const int woff = (cta >> 4) * SLOTB + b_row * 512
                   + (((cta & 15) * 32 + seg * 4) ^ ((b_row & 7) << 4));
    char* const actb = (char*)d_act_bf16;

    // ---- y partial for t=0 (tanh(h0)) ----
    {
        float th0 = tanhf(hsm[b_row * N_TILE + seg * 2]);
        float th1 = tanhf(hsm[b_row * N_TILE + seg * 2 + 1]);
        float po[NO];
        #pragma unroll
        for (int o = 0; o < NO; o++)
            po[o] = th0 * OwSm[(seg * 2) * NO + o] + th1 * OwSm[(seg * 2 + 1) * NO + o];
        #pragma unroll
        for (int o = 0; o < NO; o++) {
            po[o] += __shfl_down_sync(0xffffffffu, po[o], 4);
            po[o] += __shfl_down_sync(0xffffffffu, po[o], 2);
            po[o] += __shfl_down_sync(0xffffffffu, po[o], 1);
        }
        if (seg == 0) {
            float* yp = d_yp + ((size_t)cta * BB + b_row) * NO;
            *(float4*)yp       = make_float4(po[0], po[1], po[2], po[3]);
            *(float4*)(yp + 4) = make_float4(po[4], po[5], po[6], po[7]);
        }
    }

    for (int t = 0; t < TT; t++) {
        const char* actg = actb + (size_t)t * STEPB;

        // ---------- producer (warp 0, lane k owns slot k): phase A (chunks 0..3) ----------
        if (wid == 0 && lane < 4) {
            while (ld_acquire_gpu(&d_flag[(t * 8 + lane) * 32]) < 16u) { }
            asm volatile("fence.proxy.async;" ::: "memory");
            if (t > 0) mbar_wait(mb0 + 32 + lane * 8, 1);
            mbar_expect_tx(mb0 + lane * 8, SLOTB);
            #pragma unroll
            for (int i = 0; i < 4; i++)
                bulk_cp8k(smem_u32 + lane * SLOTB + i * 8192,
                          actg + lane * SLOTB + i * 8192, mb0 + lane * 8);
        }

        float acc[2][4];
        acc[0][0] = 0.f; acc[0][1] = 0.f; acc[0][2] = 0.f; acc[0][3] = 0.f;
        acc[1][0] = 0.f; acc[1][1] = 0.f; acc[1][2] = 0.f; acc[1][3] = 0.f;

        // ---------- chunk s (parity 0) ----------
        mbar_wait(my_full, 0);
        #pragma unroll
        for (int ks = 0; ks < 16; ks++) {
            #pragma unroll
            for (int j = 0; j < 2; j++) {
                uint32_t a0, a1, a2, a3;
                ldm_x4(a0, a1, a2, a3, abase + (wm * 2 + j) * 8192 + ((ks * 32) ^ rot60));
                mma_16816(acc[j][0], acc[j][1], acc[j][2], acc[j][3],
                          a0, a1, a2, a3, breg[2 * ks], breg[2 * ks + 1]);
            }
        }
        __syncwarp();
        if (lane == 0) mbar_arrive(my_empty);

        // ---------- producer: phase B (chunks 4..7) ----------
        if (wid == 0 && lane < 4) {
            mbar_wait(mb0 + 32 + lane * 8, 0);
            while (ld_acquire_gpu(&d_flag[(t * 8 + lane + 4) * 32]) < 16u) { }
            asm volatile("fence.proxy.async;" ::: "memory");
            mbar_expect_tx(mb0 + lane * 8, SLOTB);
            #pragma unroll
            for (int i = 0; i < 4; i++)
                bulk_cp8k(smem_u32 + lane * SLOTB + i * 8192,
                          actg + (lane + 4) * SLOTB + i * 8192, mb0 + lane * 8);
        }

        // ---------- chunk s+4 (parity 1) ----------
        mbar_wait(my_full, 1);
        #pragma unroll
        for (int ks = 0; ks < 16; ks++) {
            #pragma unroll
            for (int j = 0; j < 2; j++) {
                uint32_t a0, a1, a2, a3;
                ldm_x4(a0, a1, a2, a3, abase + (wm * 2 + j) * 8192 + ((ks * 32) ^ rot60));
                mma_16816(acc[j][0], acc[j][1], acc[j][2], acc[j][3],
                          a0, a1, a2, a3, breg[32 + 2 * ks], breg[33 + 2 * ks]);
            }
        }
        __syncwarp();
        if (lane == 0) mbar_arrive(my_empty);

        // ---------- store rec partials ----------
        #pragma unroll
        for (int j = 0; j < 2; j++) {
            int m = wm * 2 + j;
            *(float2*)(rp + (m * 16 + g) * REC_LD)     = make_float2(acc[j][0], acc[j][1]);
            *(float2*)(rp + (m * 16 + g + 8) * REC_LD) = make_float2(acc[j][2], acc[j][3]);
        }
        __syncthreads();

        // ---------- fused h update + tanh + swizzled act store (dn in registers) ----------
        float2 th;
        {
            float2 r = make_float2(0.f, 0.f);
            #pragma unroll
            for (int pl = 0; pl < 4; pl++) {
                float2 v = *(float2*)(rec + pl * REC_PLANE + b_row * REC_LD + seg * 2);
                r.x += v.x; r.y += v.y;
            }
            float2 h = *(float2*)(hsm + b_row * N_TILE + seg * 2);
            float2 hn;
            hn.x = (1.f - ALPHA) * h.x + krec * r.x + dnx;
            hn.y = (1.f - ALPHA) * h.y + krec * r.y + dny;
            *(float2*)(hsm + b_row * N_TILE + seg * 2) = hn;
            th.x = tanhf(hn.x); th.y = tanhf(hn.y);
            *(uint32_t*)(actb + (size_t)(t + 1) * STEPB + woff) = pack_bf16x2(th.x, th.y);
        }
        asm volatile("cp.async.wait_group 0;" ::: "memory");   // drain u(t+1) staging
        __syncthreads();
        if (tid == 0) red_release_add(&d_flag[((t + 1) * 8 + (cta >> 4)) * 32], 1u);

        // ---------- shadow work (off critical path) ----------
        if (t + 1 < TT) {
            // dn(t+1): u buffer ((t+1)&1), In_w smem, noise LDG
            float2 nz = *(const float2*)(noise + ((size_t)b_row * TT + (t + 1)) * NN + u0 + seg * 2);
            const float* ur = (float*)(smem_raw + OFF_U + ((t + 1) & 1) * 8192) + b_row * 32;
            float ax = 0.f, ay = 0.f;
            #pragma unroll
            for (int i = 0; i < 32; i++) {
                float uv = ur[i];
                float2 w = *(float2*)(InwSm + i * 16 + seg * 2);
                ax += uv * w.x; ay += uv * w.y;
            }
            dnx = ALPHA * (ax + nz.x);
            dny = ALPHA * (ay + nz.y);
        }
        if (t + 2 < TT) {
            cp_async16(smem_raw + OFF_U + (t & 1) * 8192 + b_row * 128 + seg * 16,
                       u + ((size_t)b_row * TT + (t + 2)) * NI + seg * 4);
        }
        asm volatile("cp.async.commit_group;" ::: "memory");

        if (wid > 0) {
            float po[NO];
            #pragma unroll
            for (int o = 0; o < NO; o++)
                po[o] = th.x * OwSm[(seg * 2) * NO + o] + th.y * OwSm[(seg * 2 + 1) * NO + o];
            #pragma unroll
            for (int o = 0; o < NO; o++) {
                po[o] += __shfl_down_sync(0xffffffffu, po[o], 4);
                po[o] += __shfl_down_sync(0xffffffffu, po[o], 2);
                po[o] += __shfl_down_sync(0xffffffffu, po[o], 1);
            }
            if (seg == 0) {
                float* yp = d_yp + (((size_t)(t + 1) * G_CTAS + cta) * BB + b_row) * NO;
                *(float4*)yp       = make_float4(po[0], po[1], po[2], po[3]);
                *(float4*)(yp + 4) = make_float4(po[4], po[5], po[6], po[7]);
            }
            if (wid == 1) {   // cover warp 0's rows (recompute tanh from hsm)
                int b0 = b_row - 4;
                float2 h2 = *(float2*)(hsm + b0 * N_TILE + seg * 2);
                float q0 = tanhf(h2.x), q1 = tanhf(h2.y);
                float p2[NO];
                #pragma unroll
                for (int o = 0; o < NO; o++)
                    p2[o] = q0 * OwSm[(seg * 2) * NO + o] + q1 * OwSm[(seg * 2 + 1) * NO + o];
                #pragma unroll
                for (int o = 0; o < NO; o++) {
                    p2[o] += __shfl_down_sync(0xffffffffu, p2[o], 4);
                    p2[o] += __shfl_down_sync(0xffffffffu, p2[o], 2);
                    p2[o] += __shfl_down_sync(0xffffffffu, p2[o], 1);
                }
                if (seg == 0) {
                    float* yp = d_yp + (((size_t)(t + 1) * G_CTAS + cta) * BB + b0) * NO;
                    *(float4*)yp       = make_float4(p2[0], p2[1], p2[2], p2[3]);
                    *(float4*)(yp + 4) = make_float4(p2[4], p2[5], p2[6], p2[7]);
                }
            }
        }
    }
}

// ---------------- y reduce ----------------
__global__ void yred_kernel(float* __restrict__ y) {
    int t = blockIdx.x;
    int b = threadIdx.x >> 3;
    int o = threadIdx.x & 7;
    float s = 0.f;
    const float* p = d_yp + (size_t)t * G_CTAS * BB * NO + b * NO + o;
    #pragma unroll 8
    for (int c = 0; c < G_CTAS; c++) s += p[(size_t)c * BB * NO];
    y[((size_t)b * (TT + 1) + t) * NO + o] = s * (1.f / (float)NN);
}

// ---------------- launcher ----------------
extern "C" void kernel_launch(void* const* d_in, const int* in_sizes, int n_in,
                              void* d_out, int out_size) {
    const float* u     = (const float*)d_in[0];
    const float* In_w  = (const float*)d_in[1];
    const float* Out_w = (const float*)d_in[2];
    const float* J     = (const float*)d_in[3];
    const float* h0    = (const float*)d_in[4];
    const float* noise = (const float*)d_in[5];
    float*       y     = (float*)d_out;

    cudaFuncSetAttribute(rnn_kernel, cudaFuncAttributeMaxDynamicSharedMemorySize, SMEM_BYTES);

    prep_kernel<<<TT, 256>>>(h0);
    rnn_kernel<<<G_CTAS, 512, SMEM_BYTES>>>(J, h0, Out_w, u, In_w, noise);
    yred_kernel<<<TT + 1, 512>>>(y);
}

// round 16
// speedup vs baseline: 1.2928x; 1.2928x over previous
#include <cuda_runtime.h>
#include <cuda_bf16.h>
#include <cstdint>

#define ALPHA   0.2f          // DT/TAU = 20/100
#define NN      2048
#define BB      64
#define TT      200
#define NI      32
#define NO      8
#define G_CTAS  128
#define N_TILE  16            // neurons per CTA

// FP8 scales (folded into krec)
#define SCALE_A 16.0f
#define SCALE_J 64.0f

// Global act layout per step (e4m3): 4 chunks x (64 rows x 512B), XOR-swizzled:
//   element (b, n): chunk = n>>9, byte kc = n&511, stored at
//   chunk*32768 + b*512 + (kc ^ ((b&7)<<4))
#define SLOTB       32768
#define STEPB       (4 * SLOTB)        // 131072 bytes per act step

// SMEM offsets
#define OFF_REC     131072             // float[4][64][20] = 20480
#define REC_LD      20
#define REC_PLANE   (64 * REC_LD)
#define OFF_HSM     151552             // float[64][16] = 4096
#define OFF_DN      155648             // float[2][64][16] = 8192
#define OFF_OW      163840             // float[16][8] = 512
#define OFF_MBAR    164352             // 4 full + 4 empty = 64
#define SMEM_BYTES  164416

// ---------------- device scratch ----------------
__device__ float          d_dn[(size_t)TT * BB * NN];
__device__ uint8_t        d_act[(size_t)(TT + 1) * STEPB];          // e4m3, swizzled
__device__ unsigned int   d_flag[(TT + 1) * 4 * 32];                // per-(t,chunk), 128B apart
__device__ float          d_yp[(size_t)(TT + 1) * G_CTAS * BB * NO];

// ---------------- PTX helpers ----------------
__device__ __forceinline__ unsigned ld_acquire_gpu(const unsigned* p) {
    unsigned v;
    asm volatile("ld.acquire.gpu.u32 %0, [%1];" : "=r"(v) : "l"(p) : "memory");
    return v;
}
__device__ __forceinline__ void red_release_add(unsigned* p, unsigned v) {
    asm volatile("red.release.gpu.global.add.u32 [%0], %1;" :: "l"(p), "r"(v) : "memory");
}
__device__ __forceinline__ void mbar_init(uint32_t mbar, uint32_t count) {
    asm volatile("mbarrier.init.shared.b64 [%0], %1;" :: "r"(mbar), "r"(count) : "memory");
}
__device__ __forceinline__ void mbar_expect_tx(uint32_t mbar, uint32_t bytes) {
    asm volatile("mbarrier.arrive.expect_tx.shared.b64 _, [%0], %1;" :: "r"(mbar), "r"(bytes) : "memory");
}
__device__ __forceinline__ void mbar_arrive(uint32_t mbar) {
    asm volatile("mbarrier.arrive.shared.b64 _, [%0];" :: "r"(mbar) : "memory");
}
__device__ __forceinline__ void mbar_wait(uint32_t mbar, int parity) {
    asm volatile(
        "{\n\t.reg .pred P;\n"
        "W%=:\n\t"
        "mbarrier.try_wait.parity.shared.b64 P, [%0], %1;\n\t"
        "@P bra D%=;\n\t"
        "bra W%=;\n"
        "D%=:\n\t}"
        :: "r"(mbar), "r"(parity) : "memory");
}
__device__ __forceinline__ void bulk_cp8k(uint32_t dst, const void* src, uint32_t mbar) {
    asm volatile(
        "cp.async.bulk.shared::cluster.global.mbarrier::complete_tx::bytes [%0], [%1], %2, [%3];"
        :: "r"(dst), "l"(src), "r"(8192u), "r"(mbar) : "memory");
}
__device__ __forceinline__ void cp_async8(void* dst_smem, const void* src_gmem) {
    unsigned s = (unsigned)__cvta_generic_to_shared(dst_smem);
    asm volatile("cp.async.ca.shared.global [%0], [%1], 8;" :: "r"(s), "l"(src_gmem) : "memory");
}
__device__ __forceinline__ void ldm_x4(uint32_t& a0, uint32_t& a1, uint32_t& a2, uint32_t& a3,
                                       uint32_t addr) {
    asm volatile("ldmatrix.sync.aligned.m8n8.x4.shared.b16 {%0,%1,%2,%3}, [%4];"
                 : "=r"(a0), "=r"(a1), "=r"(a2), "=r"(a3) : "r"(addr));
}
// fp8 e4m3 MMA: m16n8k32, A row-major, B col-major, fp32 accum
__device__ __forceinline__ void mma_fp8(float& d0, float& d1, float& d2, float& d3,
                                        uint32_t a0, uint32_t a1, uint32_t a2, uint32_t a3,
                                        uint32_t b0, uint32_t b1) {
    asm volatile("mma.sync.aligned.m16n8k32.row.col.f32.e4m3.e4m3.f32 "
                 "{%0,%1,%2,%3}, {%4,%5,%6,%7}, {%8,%9}, {%0,%1,%2,%3};"
                 : "+f"(d0), "+f"(d1), "+f"(d2), "+f"(d3)
                 : "r"(a0), "r"(a1), "r"(a2), "r"(a3), "r"(b0), "r"(b1));
}
// pack 2 floats -> 2 e4m3 in u16 (lo = first arg)
__device__ __forceinline__ uint16_t pack_fp8x2(float lo, float hi) {
    uint16_t r;
    asm("cvt.rn.satfinite.e4m3x2.f32 %0, %1, %2;" : "=h"(r) : "f"(hi), "f"(lo));
    return r;
}
__device__ __forceinline__ uint32_t pack_fp8x4(float f0, float f1, float f2, float f3) {
    uint16_t lo = pack_fp8x2(f0, f1);
    uint16_t hi = pack_fp8x2(f2, f3);
    return (uint32_t)lo | ((uint32_t)hi << 16);
}

// ---------------- prep: dn = alpha*(u@In_w^T + noise); swizzled fp8 act0; flags --------
__global__ void prep_kernel(const float* __restrict__ u,
                            const float* __restrict__ In_w,
                            const float* __restrict__ noise,
                            const float* __restrict__ h0) {
    int tid = threadIdx.x;   // 256
    if (blockIdx.y < 8) {
        int t = blockIdx.x;
        int n = blockIdx.y * 256 + tid;
        __shared__ float us[BB * NI];
        for (int idx = tid; idx < BB * NI; idx += 256) {
            int b = idx >> 5, i = idx & 31;
            us[idx] = u[((size_t)b * TT + t) * NI + i];
        }
        float4 w[8];
        #pragma unroll
        for (int i = 0; i < 8; i++) w[i] = *(const float4*)(In_w + (size_t)n * NI + i * 4);
        __syncthreads();

        const float* nz  = noise + (size_t)t * NN + n;
        float*       out = d_dn  + (size_t)t * BB * NN + n;
        for (int b = 0; b < BB; b++) {
            const float4* uu = (const float4*)(us + b * NI);
            float s = 0.f;
            #pragma unroll
            for (int i = 0; i < 8; i++) {
                float4 uv = uu[i];
                s += w[i].x * uv.x + w[i].y * uv.y + w[i].z * uv.z + w[i].w * uv.w;
            }
            out[(size_t)b * NN] = ALPHA * (s + nz[(size_t)b * TT * NN]);
        }
    } else {
        // act slot 0 = fp8(tanh(h0)*SCALE_A), swizzled
        char* base = (char*)d_act;
        int p0 = blockIdx.x * 328;
        int pe = p0 + 328; if (pe > 65536) pe = 65536;
        for (int p = p0 + tid; p < pe; p += 256) {
            int b  = p >> 10;             // batch row
            int np = p & 1023;            // neuron pair index (n = 2*np)
            int chunk = np >> 8;          // 512 fp8 per chunk = 256 pairs
            int kc    = (np & 255) * 2;
            float t0 = tanhf(h0[2 * np]) * SCALE_A;
            float t1 = tanhf(h0[2 * np + 1]) * SCALE_A;
            *(uint16_t*)(base + chunk * SLOTB + b * 512 + (kc ^ ((b & 7) << 4)))
                = pack_fp8x2(t0, t1);
        }
        if (blockIdx.x == 0) {
            for (int i = tid; i < (TT + 1) * 4; i += 256)
                d_flag[i * 32] = (i < 4) ? 32u : 0u;   // step-0 chunks pre-complete
        }
    }
}

// ---------------- persistent recurrent kernel ----------------
extern __shared__ char smem_raw[];

__global__ void __launch_bounds__(512, 1)
rnn_kernel(const float* __restrict__ J, const float* __restrict__ h0,
           const float* __restrict__ Out_w) {
    float* rec  = (float*)(smem_raw + OFF_REC);
    float* hsm  = (float*)(smem_raw + OFF_HSM);
    float* OwSm = (float*)(smem_raw + OFF_OW);

    const uint32_t smem_u32 = (uint32_t)__cvta_generic_to_shared(smem_raw);
    const uint32_t mb0 = smem_u32 + OFF_MBAR;   // full[s]=+s*8, empty[s]=+32+s*8

    const int tid  = threadIdx.x;
    const int cta  = blockIdx.x;
    const int u0   = cta * N_TILE;
    const int wid  = tid >> 5;
    const int lane = tid & 31;
    const int s    = wid >> 2;          // slot 0..3 = chunk s (512 neurons of K)
    const int nw   = (wid >> 1) & 1;    // n8 block 0..1
    const int wm   = wid & 1;           // m half (m blocks wm*2, wm*2+1)

    if (tid == 0) {
        #pragma unroll
        for (int i = 0; i < 4; i++) {
            mbar_init(mb0 + i * 8, 1);        // full[i]
            mbar_init(mb0 + 32 + i * 8, 4);   // empty[i]: 4 consumer warps per slot
        }
    }
    for (int idx = tid; idx < BB * N_TILE; idx += 512)
        hsm[idx] = h0[u0 + (idx & (N_TILE - 1))];
    for (int idx = tid; idx < N_TILE * NO; idx += 512)
        OwSm[idx] = Out_w[(size_t)(u0 + idx / NO) * NO + (idx % NO)];
    __syncthreads();

    // ---- J -> register-resident fp8 B fragments (x SCALE_J), K = [512s, 512s+512) ----
    const int n_row = u0 + nw * 8 + (lane >> 2);
    const int t4    = lane & 3;
    uint32_t breg[32];   // 16 ks x {b0,b1}
    {
        const float* Jr = J + (size_t)n_row * NN + s * 512 + 4 * t4;
        #pragma unroll
        for (int ks = 0; ks < 16; ks++) {
            float4 v0 = *(const float4*)(Jr + ks * 32);        // k = 32ks + 4t4 + [0..3]
            float4 v1 = *(const float4*)(Jr + ks * 32 + 16);   // k = 32ks + 16 + 4t4 + [0..3]
            breg[2 * ks]     = pack_fp8x4(v0.x * SCALE_J, v0.y * SCALE_J,
                                          v0.z * SCALE_J, v0.w * SCALE_J);
            breg[2 * ks + 1] = pack_fp8x4(v1.x * SCALE_J, v1.y * SCALE_J,
                                          v1.z * SCALE_J, v1.w * SCALE_J);
        }
    }

    const int b_row = tid >> 3;            // 0..63
    const int seg   = tid & 7;             // 2 neurons each
    const float krec = ALPHA / ((float)NN * SCALE_A * SCALE_J);

    // ldmatrix lane constants (swizzled 512B-row slot layout; byte geometry = bf16 case)
    const int row_in_m = (lane & 7) + ((lane >> 3) & 1) * 8;
    const int kb       = (lane >> 4) * 16;
    const int rot      = (row_in_m & 7) << 4;
    const int rot60    = rot & 0x60;
    const uint32_t abase = smem_u32 + s * SLOTB + row_in_m * 512 + (kb ^ (rot & 0x10));
    const uint32_t my_full  = mb0 + s * 8;
    const uint32_t my_empty = mb0 + 32 + s * 8;
    const int g = lane >> 2;
    float* rp   = rec + s * REC_PLANE + nw * 8 + 2 * t4;

    // act writer constants: cta owns 16 neurons = 16 bytes of chunk (cta>>5)
    const int woff = (cta >> 5) * SLOTB + b_row * 512
                   + (((cta & 31) * 16 + seg * 2) ^ ((b_row & 7) << 4));
    char* const actb = (char*)d_act;

    // prefetch dn[0]
    cp_async8(smem_raw + OFF_DN + b_row * 64 + seg * 8,
              d_dn + (size_t)b_row * NN + u0 + seg * 2);
    asm volatile("cp.async.commit_group;" ::: "memory");

    // ---- y partial for t=0 (tanh(h0)) ----
    {
        float th0 = tanhf(hsm[b_row * N_TILE + seg * 2]);
        float th1 = tanhf(hsm[b_row * N_TILE + seg * 2 + 1]);
        float po[NO];
        #pragma unroll
        for (int o = 0; o < NO; o++)
            po[o] = th0 * OwSm[(seg * 2) * NO + o] + th1 * OwSm[(seg * 2 + 1) * NO + o];
        #pragma unroll
        for (int o = 0; o < NO; o++) {
            po[o] += __shfl_down_sync(0xffffffffu, po[o], 4);
            po[o] += __shfl_down_sync(0xffffffffu, po[o], 2);
            po[o] += __shfl_down_sync(0xffffffffu, po[o], 1);
        }
        if (seg == 0) {
            float* yp = d_yp + ((size_t)cta * BB + b_row) * NO;
            *(float4*)yp       = make_float4(po[0], po[1], po[2], po[3]);
            *(float4*)(yp + 4) = make_float4(po[4], po[5], po[6], po[7]);
        }
    }

    for (int t = 0; t < TT; t++) {
        const char* actg = actb + (size_t)t * STEPB;
        const int p = t & 1;

        // ---------- producer (warp 0, lane k owns slot k): single fill phase ----------
        if (wid == 0 && lane < 4) {
            while (ld_acquire_gpu(&d_flag[(t * 4 + lane) * 32]) < 32u) { }
            asm volatile("fence.proxy.async;" ::: "memory");
            if (t > 0) mbar_wait(mb0 + 32 + lane * 8, (t - 1) & 1);
            mbar_expect_tx(mb0 + lane * 8, SLOTB);
            #pragma unroll
            for (int i = 0; i < 4; i++)
                bulk_cp8k(smem_u32 + lane * SLOTB + i * 8192,
                          actg + lane * SLOTB + i * 8192, mb0 + lane * 8);
        }

        float acc[2][4];
        acc[0][0] = 0.f; acc[0][1] = 0.f; acc[0][2] = 0.f; acc[0][3] = 0.f;
        acc[1][0] = 0.f; acc[1][1] = 0.f; acc[1][2] = 0.f; acc[1][3] = 0.f;

        // ---------- chunk s: K = 512 fp8, 16 k-steps of 32 ----------
        mbar_wait(my_full, p);
        #pragma unroll
        for (int ks = 0; ks < 16; ks++) {
            #pragma unroll
            for (int j = 0; j < 2; j++) {
                uint32_t a0, a1, a2, a3;
                ldm_x4(a0, a1, a2, a3, abase + (wm * 2 + j) * 8192 + ((ks * 32) ^ rot60));
                mma_fp8(acc[j][0], acc[j][1], acc[j][2], acc[j][3],
                        a0, a1, a2, a3, breg[2 * ks], breg[2 * ks + 1]);
            }
        }
        __syncwarp();
        if (lane == 0) mbar_arrive(my_empty);

        // ---------- store rec partials ----------
        #pragma unroll
        for (int j = 0; j < 2; j++) {
            int m = wm * 2 + j;
            *(float2*)(rp + (m * 16 + g) * REC_LD)     = make_float2(acc[j][0], acc[j][1]);
            *(float2*)(rp + (m * 16 + g + 8) * REC_LD) = make_float2(acc[j][2], acc[j][3]);
        }
        __syncthreads();

        // ---------- fused h update + tanh + swizzled fp8 act store ----------
        float2 th;
        {
            float2 r = make_float2(0.f, 0.f);
            #pragma unroll
            for (int pl = 0; pl < 4; pl++) {
                float2 v = *(float2*)(rec + pl * REC_PLANE + b_row * REC_LD + seg * 2);
                r.x += v.x; r.y += v.y;
            }
            asm volatile("cp.async.wait_group 0;" ::: "memory");
            float2 dn = *(float2*)(smem_raw + OFF_DN + (t & 1) * 4096 + b_row * 64 + seg * 8);
            float2 h  = *(float2*)(hsm + b_row * N_TILE + seg * 2);
            float2 hn;
            hn.x = (1.f - ALPHA) * h.x + krec * r.x + dn.x;
            hn.y = (1.f - ALPHA) * h.y + krec * r.y + dn.y;
            *(float2*)(hsm + b_row * N_TILE + seg * 2) = hn;
            th.x = tanhf(hn.x); th.y = tanhf(hn.y);
            *(uint16_t*)(actb + (size_t)(t + 1) * STEPB + woff)
                = pack_fp8x2(th.x * SCALE_A, th.y * SCALE_A);
        }
        __syncthreads();
        if (tid == 0) red_release_add(&d_flag[((t + 1) * 4 + (cta >> 5)) * 32], 1u);

        // ---------- shadow work (off critical path; warp 0 exempt) ----------
        if (t + 1 < TT) {
            cp_async8(smem_raw + OFF_DN + ((t + 1) & 1) * 4096 + b_row * 64 + seg * 8,
                      d_dn + ((size_t)(t + 1) * BB + b_row) * NN + u0 + seg * 2);
            asm volatile("cp.async.commit_group;" ::: "memory");
        }
        if (wid > 0) {
            float po[NO];
            #pragma unroll
            for (int o = 0; o < NO; o++)
                po[o] = th.x * OwSm[(seg * 2) * NO + o] + th.y * OwSm[(seg * 2 + 1) * NO + o];
            #pragma unroll
            for (int o = 0; o < NO; o++) {
                po[o] += __shfl_down_sync(0xffffffffu, po[o], 4);
                po[o] += __shfl_down_sync(0xffffffffu, po[o], 2);
                po[o] += __shfl_down_sync(0xffffffffu, po[o], 1);
            }
            if (seg == 0) {
                float* yp = d_yp + (((size_t)(t + 1) * G_CTAS + cta) * BB + b_row) * NO;
                *(float4*)yp       = make_float4(po[0], po[1], po[2], po[3]);
                *(float4*)(yp + 4) = make_float4(po[4], po[5], po[6], po[7]);
            }
            if (wid == 1) {   // cover warp 0's rows (recompute tanh from hsm)
                int b0 = b_row - 4;
                float2 h2 = *(float2*)(hsm + b0 * N_TILE + seg * 2);
                float q0 = tanhf(h2.x), q1 = tanhf(h2.y);
                float p2[NO];
                #pragma unroll
                for (int o = 0; o < NO; o++)
                    p2[o] = q0 * OwSm[(seg * 2) * NO + o] + q1 * OwSm[(seg * 2 + 1) * NO + o];
                #pragma unroll
                for (int o = 0; o < NO; o++) {
                    p2[o] += __shfl_down_sync(0xffffffffu, p2[o], 4);
                    p2[o] += __shfl_down_sync(0xffffffffu, p2[o], 2);
                    p2[o] += __shfl_down_sync(0xffffffffu, p2[o], 1);
                }
                if (seg == 0) {
                    float* yp = d_yp + (((size_t)(t + 1) * G_CTAS + cta) * BB + b0) * NO;
                    *(float4*)yp       = make_float4(p2[0], p2[1], p2[2], p2[3]);
                    *(float4*)(yp + 4) = make_float4(p2[4], p2[5], p2[6], p2[7]);
                }
            }
        }
    }
}

// ---------------- y reduce ----------------
__global__ void yred_kernel(float* __restrict__ y) {
    int t = blockIdx.x;
    int b = threadIdx.x >> 3;
    int o = threadIdx.x & 7;
    float s = 0.f;
    const float* p = d_yp + (size_t)t * G_CTAS * BB * NO + b * NO + o;
    #pragma unroll 8
    for (int c = 0; c < G_CTAS; c++) s += p[(size_t)c * BB * NO];
    y[((size_t)b * (TT + 1) + t) * NO + o] = s * (1.f / (float)NN);
}

// ---------------- launcher ----------------
extern "C" void kernel_launch(void* const* d_in, const int* in_sizes, int n_in,
                              void* d_out, int out_size) {
    const float* u     = (const float*)d_in[0];
    const float* In_w  = (const float*)d_in[1];
    const float* Out_w = (const float*)d_in[2];
    const float* J     = (const float*)d_in[3];
    const float* h0    = (const float*)d_in[4];
    const float* noise = (const float*)d_in[5];
    float*       y     = (float*)d_out;

    cudaFuncSetAttribute(rnn_kernel, cudaFuncAttributeMaxDynamicSharedMemorySize, SMEM_BYTES);

    dim3 gprep(TT, 9);
    prep_kernel<<<gprep, 256>>>(u, In_w, noise, h0);
    rnn_kernel<<<G_CTAS, 512, SMEM_BYTES>>>(J, h0, Out_w);
    yred_kernel<<<TT + 1, 512>>>(y);
}

// round 17
// speedup vs baseline: 1.3428x; 1.0387x over previous
#include <cuda_runtime.h>
#include <cuda_bf16.h>
#include <cstdint>

#define ALPHA   0.2f          // DT/TAU = 20/100
#define NN      2048
#define BB      64
#define TT      200
#define NI      32
#define NO      8
#define G_CTAS  128
#define N_TILE  16            // neurons per CTA

// FP8 scales (folded into krec)
#define SCALE_A 16.0f
#define SCALE_J 64.0f

// Global act layout per step (e4m3): 4 chunks x (64 rows x 512B), XOR-swizzled:
//   element (b, n): chunk = n>>9, byte kc = n&511, stored at
//   chunk*32768 + b*512 + (kc ^ ((b&7)<<4))
#define SLOTB       32768
#define STEPB       (4 * SLOTB)        // 131072 bytes per act step

// SMEM offsets
#define OFF_REC     131072             // float[4][64][20] = 20480
#define REC_LD      20
#define REC_PLANE   (64 * REC_LD)
#define OFF_HSM     151552             // float[64][16] = 4096
#define OFF_DN      155648             // float[2][64][16] = 8192
#define OFF_OW      163840             // float[16][8] = 512
#define OFF_MBAR    164352             // 4 full + 4 empty = 64
#define SMEM_BYTES  164416

// ---------------- device scratch ----------------
__device__ float          d_dn[(size_t)TT * BB * NN];
__device__ uint8_t        d_act[(size_t)(TT + 1) * STEPB];          // e4m3, swizzled
__device__ unsigned int   d_flag[(TT + 1) * 4 * 32];                // per-(t,chunk), 128B apart
__device__ float          d_yp[(size_t)(TT + 1) * G_CTAS * BB * NO];

// ---------------- PTX helpers ----------------
__device__ __forceinline__ float tanh_fast(float x) {
    float r; asm("tanh.approx.f32 %0, %1;" : "=f"(r) : "f"(x)); return r;
}
__device__ __forceinline__ unsigned ld_acquire_gpu(const unsigned* p) {
    unsigned v;
    asm volatile("ld.acquire.gpu.u32 %0, [%1];" : "=r"(v) : "l"(p) : "memory");
    return v;
}
__device__ __forceinline__ void red_release_add(unsigned* p, unsigned v) {
    asm volatile("red.release.gpu.global.add.u32 [%0], %1;" :: "l"(p), "r"(v) : "memory");
}
__device__ __forceinline__ void mbar_init(uint32_t mbar, uint32_t count) {
    asm volatile("mbarrier.init.shared.b64 [%0], %1;" :: "r"(mbar), "r"(count) : "memory");
}
__device__ __forceinline__ void mbar_expect_tx(uint32_t mbar, uint32_t bytes) {
    asm volatile("mbarrier.arrive.expect_tx.shared.b64 _, [%0], %1;" :: "r"(mbar), "r"(bytes) : "memory");
}
__device__ __forceinline__ void mbar_arrive(uint32_t mbar) {
    asm volatile("mbarrier.arrive.shared.b64 _, [%0];" :: "r"(mbar) : "memory");
}
__device__ __forceinline__ void mbar_wait(uint32_t mbar, int parity) {
    asm volatile(
        "{\n\t.reg .pred P;\n"
        "W%=:\n\t"
        "mbarrier.try_wait.parity.shared.b64 P, [%0], %1;\n\t"
        "@P bra D%=;\n\t"
        "bra W%=;\n"
        "D%=:\n\t}"
        :: "r"(mbar), "r"(parity) : "memory");
}
__device__ __forceinline__ void bulk_cp8k(uint32_t dst, const void* src, uint32_t mbar) {
    asm volatile(
        "cp.async.bulk.shared::cluster.global.mbarrier::complete_tx::bytes [%0], [%1], %2, [%3];"
        :: "r"(dst), "l"(src), "r"(8192u), "r"(mbar) : "memory");
}
__device__ __forceinline__ void cp_async8(void* dst_smem, const void* src_gmem) {
    unsigned s = (unsigned)__cvta_generic_to_shared(dst_smem);
    asm volatile("cp.async.ca.shared.global [%0], [%1], 8;" :: "r"(s), "l"(src_gmem) : "memory");
}
__device__ __forceinline__ void ldm_x4(uint32_t& a0, uint32_t& a1, uint32_t& a2, uint32_t& a3,
                                       uint32_t addr) {
    asm volatile("ldmatrix.sync.aligned.m8n8.x4.shared.b16 {%0,%1,%2,%3}, [%4];"
                 : "=r"(a0), "=r"(a1), "=r"(a2), "=r"(a3) : "r"(addr));
}
// fp8 e4m3 MMA: m16n8k32, A row-major, B col-major, fp32 accum
__device__ __forceinline__ void mma_fp8(float& d0, float& d1, float& d2, float& d3,
                                        uint32_t a0, uint32_t a1, uint32_t a2, uint32_t a3,
                                        uint32_t b0, uint32_t b1) {
    asm volatile("mma.sync.aligned.m16n8k32.row.col.f32.e4m3.e4m3.f32 "
                 "{%0,%1,%2,%3}, {%4,%5,%6,%7}, {%8,%9}, {%0,%1,%2,%3};"
                 : "+f"(d0), "+f"(d1), "+f"(d2), "+f"(d3)
                 : "r"(a0), "r"(a1), "r"(a2), "r"(a3), "r"(b0), "r"(b1));
}
// pack 2 floats -> 2 e4m3 in u16 (lo = first arg)
__device__ __forceinline__ uint16_t pack_fp8x2(float lo, float hi) {
    uint16_t r;
    asm("cvt.rn.satfinite.e4m3x2.f32 %0, %1, %2;" : "=h"(r) : "f"(hi), "f"(lo));
    return r;
}
__device__ __forceinline__ uint32_t pack_fp8x4(float f0, float f1, float f2, float f3) {
    uint16_t lo = pack_fp8x2(f0, f1);
    uint16_t hi = pack_fp8x2(f2, f3);
    return (uint32_t)lo | ((uint32_t)hi << 16);
}

// ---------------- prep: dn = alpha*(u@In_w^T + noise); swizzled fp8 act0; flags --------
__global__ void prep_kernel(const float* __restrict__ u,
                            const float* __restrict__ In_w,
                            const float* __restrict__ noise,
                            const float* __restrict__ h0) {
    int tid = threadIdx.x;   // 256
    if (blockIdx.y < 8) {
        int t = blockIdx.x;
        int n = blockIdx.y * 256 + tid;
        __shared__ float us[BB * NI];
        for (int idx = tid; idx < BB * NI; idx += 256) {
            int b = idx >> 5, i = idx & 31;
            us[idx] = u[((size_t)b * TT + t) * NI + i];
        }
        float4 w[8];
        #pragma unroll
        for (int i = 0; i < 8; i++) w[i] = *(const float4*)(In_w + (size_t)n * NI + i * 4);
        __syncthreads();

        const float* nz  = noise + (size_t)t * NN + n;
        float*       out = d_dn  + (size_t)t * BB * NN + n;
        // 2 batch rows x 2 half-dot accumulators = 4 independent FMA chains
        for (int b = 0; b < BB; b += 2) {
            const float4* uu0 = (const float4*)(us + b * NI);
            const float4* uu1 = (const float4*)(us + (b + 1) * NI);
            float nz0 = nz[(size_t)b * TT * NN];
            float nz1 = nz[(size_t)(b + 1) * TT * NN];
            float s0a = 0.f, s0b = 0.f, s1a = 0.f, s1b = 0.f;
            #pragma unroll
            for (int i = 0; i < 4; i++) {
                float4 v0 = uu0[i], v1 = uu1[i];
                s0a += w[i].x * v0.x + w[i].y * v0.y + w[i].z * v0.z + w[i].w * v0.w;
                s1a += w[i].x * v1.x + w[i].y * v1.y + w[i].z * v1.z + w[i].w * v1.w;
            }
            #pragma unroll
            for (int i = 4; i < 8; i++) {
                float4 v0 = uu0[i], v1 = uu1[i];
                s0b += w[i].x * v0.x + w[i].y * v0.y + w[i].z * v0.z + w[i].w * v0.w;
                s1b += w[i].x * v1.x + w[i].y * v1.y + w[i].z * v1.z + w[i].w * v1.w;
            }
            out[(size_t)b * NN]       = ALPHA * (s0a + s0b + nz0);
            out[(size_t)(b + 1) * NN] = ALPHA * (s1a + s1b + nz1);
        }
    } else {
        // act slot 0 = fp8(tanh(h0)*SCALE_A), swizzled
        char* base = (char*)d_act;
        int p0 = blockIdx.x * 328;
        int pe = p0 + 328; if (pe > 65536) pe = 65536;
        for (int p = p0 + tid; p < pe; p += 256) {
            int b  = p >> 10;             // batch row
            int np = p & 1023;            // neuron pair index (n = 2*np)
            int chunk = np >> 8;          // 512 fp8 per chunk = 256 pairs
            int kc    = (np & 255) * 2;
            float t0 = tanh_fast(h0[2 * np]) * SCALE_A;
            float t1 = tanh_fast(h0[2 * np + 1]) * SCALE_A;
            *(uint16_t*)(base + chunk * SLOTB + b * 512 + (kc ^ ((b & 7) << 4)))
                = pack_fp8x2(t0, t1);
        }
        if (blockIdx.x == 0) {
            for (int i = tid; i < (TT + 1) * 4; i += 256)
                d_flag[i * 32] = (i < 4) ? 32u : 0u;   // step-0 chunks pre-complete
        }
    }
}

// ---------------- persistent recurrent kernel ----------------
extern __shared__ char smem_raw[];

__global__ void __launch_bounds__(512, 1)
rnn_kernel(const float* __restrict__ J, const float* __restrict__ h0,
           const float* __restrict__ Out_w) {
    float* rec  = (float*)(smem_raw + OFF_REC);
    float* hsm  = (float*)(smem_raw + OFF_HSM);
    float* OwSm = (float*)(smem_raw + OFF_OW);

    const uint32_t smem_u32 = (uint32_t)__cvta_generic_to_shared(smem_raw);
    const uint32_t mb0 = smem_u32 + OFF_MBAR;   // full[s]=+s*8, empty[s]=+32+s*8

    const int tid  = threadIdx.x;
    const int cta  = blockIdx.x;
    const int u0   = cta * N_TILE;
    const int wid  = tid >> 5;
    const int lane = tid & 31;
    const int s    = wid >> 2;          // slot 0..3 = chunk s (512 neurons of K)
    const int nw   = (wid >> 1) & 1;    // n8 block 0..1
    const int wm   = wid & 1;           // m half (m blocks wm*2, wm*2+1)

    if (tid == 0) {
        #pragma unroll
        for (int i = 0; i < 4; i++) {
            mbar_init(mb0 + i * 8, 1);        // full[i]
            mbar_init(mb0 + 32 + i * 8, 4);   // empty[i]: 4 consumer warps per slot
        }
    }
    for (int idx = tid; idx < BB * N_TILE; idx += 512)
        hsm[idx] = h0[u0 + (idx & (N_TILE - 1))];
    for (int idx = tid; idx < N_TILE * NO; idx += 512)
        OwSm[idx] = Out_w[(size_t)(u0 + idx / NO) * NO + (idx % NO)];
    __syncthreads();

    // ---- J -> register-resident fp8 B fragments (x SCALE_J), K = [512s, 512s+512) ----
    const int n_row = u0 + nw * 8 + (lane >> 2);
    const int t4    = lane & 3;
    uint32_t breg[32];   // 16 ks x {b0,b1}
    {
        const float* Jr = J + (size_t)n_row * NN + s * 512 + 4 * t4;
        #pragma unroll
        for (int ks = 0; ks < 16; ks++) {
            float4 v0 = *(const float4*)(Jr + ks * 32);
            float4 v1 = *(const float4*)(Jr + ks * 32 + 16);
            breg[2 * ks]     = pack_fp8x4(v0.x * SCALE_J, v0.y * SCALE_J,
                                          v0.z * SCALE_J, v0.w * SCALE_J);
            breg[2 * ks + 1] = pack_fp8x4(v1.x * SCALE_J, v1.y * SCALE_J,
                                          v1.z * SCALE_J, v1.w * SCALE_J);
        }
    }

    const int b_row = tid >> 3;            // 0..63
    const int seg   = tid & 7;             // 2 neurons each
    const float krec = ALPHA / ((float)NN * SCALE_A * SCALE_J);

    // ldmatrix lane constants (swizzled 512B-row slot layout)
    const int row_in_m = (lane & 7) + ((lane >> 3) & 1) * 8;
    const int kb       = (lane >> 4) * 16;
    const int rot      = (row_in_m & 7) << 4;
    const int rot60    = rot & 0x60;
    const uint32_t abase = smem_u32 + s * SLOTB + row_in_m * 512 + (kb ^ (rot & 0x10));
    const uint32_t my_full  = mb0 + s * 8;
    const uint32_t my_empty = mb0 + 32 + s * 8;
    const int g = lane >> 2;
    float* rp   = rec + s * REC_PLANE + nw * 8 + 2 * t4;

    // act writer constants: cta owns 16 neurons = 16 bytes of chunk (cta>>5)
    const int woff = (cta >> 5) * SLOTB + b_row * 512
                   + (((cta & 31) * 16 + seg * 2) ^ ((b_row & 7) << 4));
    char* const actb = (char*)d_act;

    // prefetch dn[0]
    cp_async8(smem_raw + OFF_DN + b_row * 64 + seg * 8,
              d_dn + (size_t)b_row * NN + u0 + seg * 2);
    asm volatile("cp.async.commit_group;" ::: "memory");

    // ---- y partial for t=0 (tanh(h0)) ----
    {
        float th0 = tanh_fast(hsm[b_row * N_TILE + seg * 2]);
        float th1 = tanh_fast(hsm[b_row * N_TILE + seg * 2 + 1]);
        float po[NO];
        #pragma unroll
        for (int o = 0; o < NO; o++)
            po[o] = th0 * OwSm[(seg * 2) * NO + o] + th1 * OwSm[(seg * 2 + 1) * NO + o];
        #pragma unroll
        for (int o = 0; o < NO; o++) {
            po[o] += __shfl_down_sync(0xffffffffu, po[o], 4);
            po[o] += __shfl_down_sync(0xffffffffu, po[o], 2);
            po[o] += __shfl_down_sync(0xffffffffu, po[o], 1);
        }
        if (seg == 0) {
            float* yp = d_yp + ((size_t)cta * BB + b_row) * NO;
            *(float4*)yp       = make_float4(po[0], po[1], po[2], po[3]);
            *(float4*)(yp + 4) = make_float4(po[4], po[5], po[6], po[7]);
        }
    }

    for (int t = 0; t < TT; t++) {
        const char* actg = actb + (size_t)t * STEPB;
        const int p = t & 1;

        // ---------- producer (warp 0, lane k owns slot k): single fill phase ----------
        if (wid == 0 && lane < 4) {
            while (ld_acquire_gpu(&d_flag[(t * 4 + lane) * 32]) < 32u) { }
            asm volatile("fence.proxy.async;" ::: "memory");
            if (t > 0) mbar_wait(mb0 + 32 + lane * 8, (t - 1) & 1);
            mbar_expect_tx(mb0 + lane * 8, SLOTB);
            #pragma unroll
            for (int i = 0; i < 4; i++)
                bulk_cp8k(smem_u32 + lane * SLOTB + i * 8192,
                          actg + lane * SLOTB + i * 8192, mb0 + lane * 8);
        }

        float acc[2][4];
        acc[0][0] = 0.f; acc[0][1] = 0.f; acc[0][2] = 0.f; acc[0][3] = 0.f;
        acc[1][0] = 0.f; acc[1][1] = 0.f; acc[1][2] = 0.f; acc[1][3] = 0.f;

        // ---------- chunk s: K = 512 fp8, 16 k-steps of 32 ----------
        mbar_wait(my_full, p);
        #pragma unroll
        for (int ks = 0; ks < 16; ks++) {
            #pragma unroll
            for (int j = 0; j < 2; j++) {
                uint32_t a0, a1, a2, a3;
                ldm_x4(a0, a1, a2, a3, abase + (wm * 2 + j) * 8192 + ((ks * 32) ^ rot60));
                mma_fp8(acc[j][0], acc[j][1], acc[j][2], acc[j][3],
                        a0, a1, a2, a3, breg[2 * ks], breg[2 * ks + 1]);
            }
        }
        __syncwarp();
        if (lane == 0) mbar_arrive(my_empty);

        // ---------- store rec partials ----------
        #pragma unroll
        for (int j = 0; j < 2; j++) {
            int m = wm * 2 + j;
            *(float2*)(rp + (m * 16 + g) * REC_LD)     = make_float2(acc[j][0], acc[j][1]);
            *(float2*)(rp + (m * 16 + g + 8) * REC_LD) = make_float2(acc[j][2], acc[j][3]);
        }
        __syncthreads();

        // ---------- fused h update + fast tanh + swizzled fp8 act store ----------
        float2 th;
        {
            float2 r = make_float2(0.f, 0.f);
            #pragma unroll
            for (int pl = 0; pl < 4; pl++) {
                float2 v = *(float2*)(rec + pl * REC_PLANE + b_row * REC_LD + seg * 2);
                r.x += v.x; r.y += v.y;
            }
            asm volatile("cp.async.wait_group 0;" ::: "memory");
            float2 dn = *(float2*)(smem_raw + OFF_DN + (t & 1) * 4096 + b_row * 64 + seg * 8);
            float2 h  = *(float2*)(hsm + b_row * N_TILE + seg * 2);
            float2 hn;
            hn.x = (1.f - ALPHA) * h.x + krec * r.x + dn.x;
            hn.y = (1.f - ALPHA) * h.y + krec * r.y + dn.y;
            *(float2*)(hsm + b_row * N_TILE + seg * 2) = hn;
            th.x = tanh_fast(hn.x); th.y = tanh_fast(hn.y);
            *(uint16_t*)(actb + (size_t)(t + 1) * STEPB + woff)
                = pack_fp8x2(th.x * SCALE_A, th.y * SCALE_A);
        }
        __syncthreads();
        if (tid == 0) red_release_add(&d_flag[((t + 1) * 4 + (cta >> 5)) * 32], 1u);

        // ---------- shadow work (off critical path; warp 0 exempt) ----------
        if (t + 1 < TT) {
            cp_async8(smem_raw + OFF_DN + ((t + 1) & 1) * 4096 + b_row * 64 + seg * 8,
                      d_dn + ((size_t)(t + 1) * BB + b_row) * NN + u0 + seg * 2);
            asm volatile("cp.async.commit_group;" ::: "memory");
        }
        if (wid > 0) {
            float po[NO];
            #pragma unroll
            for (int o = 0; o < NO; o++)
                po[o] = th.x * OwSm[(seg * 2) * NO + o] + th.y * OwSm[(seg * 2 + 1) * NO + o];
            #pragma unroll
            for (int o = 0; o < NO; o++) {
                po[o] += __shfl_down_sync(0xffffffffu, po[o], 4);
                po[o] += __shfl_down_sync(0xffffffffu, po[o], 2);
                po[o] += __shfl_down_sync(0xffffffffu, po[o], 1);
            }
            if (seg == 0) {
                float* yp = d_yp + (((size_t)(t + 1) * G_CTAS + cta) * BB + b_row) * NO;
                *(float4*)yp       = make_float4(po[0], po[1], po[2], po[3]);
                *(float4*)(yp + 4) = make_float4(po[4], po[5], po[6], po[7]);
            }
            if (wid == 1) {   // cover warp 0's rows (recompute tanh from hsm)
                int b0 = b_row - 4;
                float2 h2 = *(float2*)(hsm + b0 * N_TILE + seg * 2);
                float q0 = tanh_fast(h2.x), q1 = tanh_fast(h2.y);
                float p2[NO];
                #pragma unroll
                for (int o = 0; o < NO; o++)
                    p2[o] = q0 * OwSm[(seg * 2) * NO + o] + q1 * OwSm[(seg * 2 + 1) * NO + o];
                #pragma unroll
                for (int o = 0; o < NO; o++) {
                    p2[o] += __shfl_down_sync(0xffffffffu, p2[o], 4);
                    p2[o] += __shfl_down_sync(0xffffffffu, p2[o], 2);
                    p2[o] += __shfl_down_sync(0xffffffffu, p2[o], 1);
                }
                if (seg == 0) {
                    float* yp = d_yp + (((size_t)(t + 1) * G_CTAS + cta) * BB + b0) * NO;
                    *(float4*)yp       = make_float4(p2[0], p2[1], p2[2], p2[3]);
                    *(float4*)(yp + 4) = make_float4(p2[4], p2[5], p2[6], p2[7]);
                }
            }
        }
    }
}

// ---------------- y reduce ----------------
__global__ void yred_kernel(float* __restrict__ y) {
    int t = blockIdx.x;
    int b = threadIdx.x >> 3;
    int o = threadIdx.x & 7;
    float s = 0.f;
    const float* p = d_yp + (size_t)t * G_CTAS * BB * NO + b * NO + o;
    #pragma unroll 8
    for (int c = 0; c < G_CTAS; c++) s += p[(size_t)c * BB * NO];
    y[((size_t)b * (TT + 1) + t) * NO + o] = s * (1.f / (float)NN);
}

// ---------------- launcher ----------------
extern "C" void kernel_launch(void* const* d_in, const int* in_sizes, int n_in,
                              void* d_out, int out_size) {
    const float* u     = (const float*)d_in[0];
    const float* In_w  = (const float*)d_in[1];
    const float* Out_w = (const float*)d_in[2];
    const float* J     = (const float*)d_in[3];
    const float* h0    = (const float*)d_in[4];
    const float* noise = (const float*)d_in[5];
    float*       y     = (float*)d_out;

    cudaFuncSetAttribute(rnn_kernel, cudaFuncAttributeMaxDynamicSharedMemorySize, SMEM_BYTES);

    dim3 gprep(TT, 9);
    prep_kernel<<<gprep, 256>>>(u, In_w, noise, h0);
    rnn_kernel<<<G_CTAS, 512, SMEM_BYTES>>>(J, h0, Out_w);
    yred_kernel<<<TT + 1, 512>>>(y);
}